// round 1
// baseline (speedup 1.0000x reference)
#include <cuda_runtime.h>
#include <cuda_bf16.h>

// Problem constants (from reference)
#define NUM_BINS_X 1024
#define NUM_BINS_Y 1024
#define NUM_NODES 2000000
#define NUM_PHYSICAL 2000000
#define KMAX 4
// bsx = bsy = 1.0, origins = 0.0
// scale = 1 / (bsx*bsy*UNIT_PIN_CAPACITY) = 10.0
#define OUT_SCALE 10.0f
#define SQRT2F 1.41421356237309515f

__global__ void zero_out_kernel(float4* __restrict__ out) {
    int i = blockIdx.x * blockDim.x + threadIdx.x;
    out[i] = make_float4(0.f, 0.f, 0.f, 0.f);
}

__global__ __launch_bounds__(256) void pin_util_kernel(
    const float* __restrict__ pos,
    const float* __restrict__ node_size_x,
    const float* __restrict__ node_size_y,
    const float* __restrict__ pin_weights,
    float* __restrict__ out)
{
    int i = blockIdx.x * 256 + threadIdx.x;
    if (i >= NUM_PHYSICAL) return;

    float nsx = node_size_x[i];
    float nsy = node_size_y[i];
    float x   = pos[i];
    float y   = pos[NUM_NODES + i];
    float pw  = pin_weights[i];

    float hx = 0.5f * fmaxf(nsx, SQRT2F);
    float hy = 0.5f * fmaxf(nsy, SQRT2F);
    float cx = x + 0.5f * nsx;
    float cy = y + 0.5f * nsy;
    float xmin = cx - hx, xmax = cx + hx;
    float ymin = cy - hy, ymax = cy + hy;

    // bin_size = 1.0, origin = 0.0 -> exact floor math
    int blx = max(0, (int)floorf(xmin));
    int bhx = min((int)floorf(xmax) + 1, NUM_BINS_X);
    int bly = max(0, (int)floorf(ymin));
    int bhy = min((int)floorf(ymax) + 1, NUM_BINS_Y);

    int nx = bhx - blx; nx = nx > KMAX ? KMAX : nx;
    int ny = bhy - bly; ny = ny > KMAX ? KMAX : ny;
    if (nx <= 0 || ny <= 0) return;

    // density * final scale folded together
    float dens = (OUT_SCALE * pw) / (4.0f * hx * hy);

    // Precompute y-axis overlaps (<= 3 nonzero in practice, KMAX=4 for safety)
    float ovy[KMAX];
    #pragma unroll
    for (int k = 0; k < KMAX; ++k) {
        float b = (float)(bly + k);
        ovy[k] = fminf(b + 1.0f, ymax) - fmaxf(b, ymin);
    }

    for (int kx = 0; kx < nx; ++kx) {
        float bx = (float)(blx + kx);
        float ovx = fminf(bx + 1.0f, xmax) - fmaxf(bx, xmin);
        float c = dens * ovx;
        float* row = out + (blx + kx) * NUM_BINS_Y + bly;
        for (int ky = 0; ky < ny; ++ky) {
            atomicAdd(row + ky, c * ovy[ky]);   // return unused -> REDG
        }
    }
}

extern "C" void kernel_launch(void* const* d_in, const int* in_sizes, int n_in,
                              void* d_out, int out_size) {
    const float* pos  = (const float*)d_in[0];
    const float* nsx  = (const float*)d_in[1];
    const float* nsy  = (const float*)d_in[2];
    const float* pw   = (const float*)d_in[3];
    float* out = (float*)d_out;

    // out_size = 1024*1024; zero it (poisoned by harness)
    int n4 = (NUM_BINS_X * NUM_BINS_Y) / 4;           // 262144
    zero_out_kernel<<<n4 / 256, 256>>>((float4*)out);

    int grid = (NUM_PHYSICAL + 255) / 256;
    pin_util_kernel<<<grid, 256>>>(pos, nsx, nsy, pw, out);
}

// round 2
// speedup vs baseline: 1.3914x; 1.3914x over previous
#include <cuda_runtime.h>
#include <cuda_bf16.h>

// Problem constants (from reference)
#define NUM_BINS_X 1024
#define NUM_BINS_Y 1024
#define NUM_NODES 2000000
#define NUM_PHYSICAL 2000000
#define KMAX 4
// bsx = bsy = 1.0, origins = 0.0
// scale = 1 / (bsx*bsy*UNIT_PIN_CAPACITY) = 10.0
#define OUT_SCALE 10.0f
#define SQRT2F 1.41421356237309515f

__global__ void zero_out_kernel(float4* __restrict__ out) {
    int i = blockIdx.x * blockDim.x + threadIdx.x;
    out[i] = make_float4(0.f, 0.f, 0.f, 0.f);
}

__device__ __forceinline__ void red_f32(float* p, float v) {
    asm volatile("red.global.add.f32 [%0], %1;" :: "l"(p), "f"(v) : "memory");
}
__device__ __forceinline__ void red_v2f32(float* p, float a, float b) {
    asm volatile("red.global.add.v2.f32 [%0], {%1, %2};"
                 :: "l"(p), "f"(a), "f"(b) : "memory");
}

__global__ __launch_bounds__(256) void pin_util_kernel(
    const float* __restrict__ pos,
    const float* __restrict__ node_size_x,
    const float* __restrict__ node_size_y,
    const float* __restrict__ pin_weights,
    float* __restrict__ out)
{
    int i = blockIdx.x * 256 + threadIdx.x;
    if (i >= NUM_PHYSICAL) return;

    float nsx = node_size_x[i];
    float nsy = node_size_y[i];
    float x   = pos[i];
    float y   = pos[NUM_NODES + i];
    float pw  = pin_weights[i];

    float hx = 0.5f * fmaxf(nsx, SQRT2F);
    float hy = 0.5f * fmaxf(nsy, SQRT2F);
    float cx = x + 0.5f * nsx;
    float cy = y + 0.5f * nsy;
    float xmin = cx - hx, xmax = cx + hx;
    float ymin = cy - hy, ymax = cy + hy;

    // bin_size = 1.0, origin = 0.0 -> exact floor math
    int blx = max(0, (int)floorf(xmin));
    int bhx = min((int)floorf(xmax) + 1, NUM_BINS_X);
    int bly = max(0, (int)floorf(ymin));
    int bhy = min((int)floorf(ymax) + 1, NUM_BINS_Y);

    int nx = bhx - blx; nx = nx > KMAX ? KMAX : nx;
    int ny = bhy - bly; ny = ny > KMAX ? KMAX : ny;
    if (nx <= 0 || ny <= 0) return;

    // density * final scale folded together
    float dens = (OUT_SCALE * pw) / (4.0f * hx * hy);

    // Precompute y-axis overlaps (ny <= 3 in practice; KMAX=4 for safety)
    float ovy[KMAX];
    #pragma unroll
    for (int k = 0; k < KMAX; ++k) {
        float b = (float)(bly + k);
        ovy[k] = fminf(b + 1.0f, ymax) - fmaxf(b, ymin);
    }

    for (int kx = 0; kx < nx; ++kx) {
        float bx = (float)(blx + kx);
        float ovx = fminf(bx + 1.0f, xmax) - fmaxf(bx, xmin);
        float c = dens * ovx;
        float* row = out + (blx + kx) * NUM_BINS_Y;

        // Exact-cover of [bly, bly+ny) with alignment-respecting v2 + scalar REDs.
        int p = bly, e = bly + ny, k = 0;
        if (p & 1) {                       // leading unaligned scalar
            red_f32(row + p, c * ovy[k]);
            ++p; ++k;
        }
        #pragma unroll
        for (int t = 0; t < KMAX / 2; ++t) {
            if (p + 2 <= e) {              // 8B-aligned pair
                red_v2f32(row + p, c * ovy[k], c * ovy[k + 1]);
                p += 2; k += 2;
            }
        }
        if (p < e) {                       // trailing scalar
            red_f32(row + p, c * ovy[k]);
        }
    }
}

extern "C" void kernel_launch(void* const* d_in, const int* in_sizes, int n_in,
                              void* d_out, int out_size) {
    const float* pos  = (const float*)d_in[0];
    const float* nsx  = (const float*)d_in[1];
    const float* nsy  = (const float*)d_in[2];
    const float* pw   = (const float*)d_in[3];
    float* out = (float*)d_out;

    // out_size = 1024*1024; zero it (poisoned by harness)
    int n4 = (NUM_BINS_X * NUM_BINS_Y) / 4;           // 262144
    zero_out_kernel<<<n4 / 256, 256>>>((float4*)out);

    int grid = (NUM_PHYSICAL + 255) / 256;
    pin_util_kernel<<<grid, 256>>>(pos, nsx, nsy, pw, out);
}

// round 3
// speedup vs baseline: 1.6952x; 1.2183x over previous
#include <cuda_runtime.h>
#include <cuda_bf16.h>

// Problem constants (from reference)
#define NUM_BINS_X 1024
#define NUM_BINS_Y 1024
#define NUM_NODES 2000000
#define NUM_PHYSICAL 2000000
#define KMAX 4
// bsx = bsy = 1.0, origins = 0.0; scale = 1/(1*1*0.1) = 10
#define OUT_SCALE 10.0f
#define SQRT2F 1.41421356237309515f

__global__ void zero_out_kernel(float4* __restrict__ out) {
    int i = blockIdx.x * blockDim.x + threadIdx.x;
    out[i] = make_float4(0.f, 0.f, 0.f, 0.f);
}

__device__ __forceinline__ void red_v4f32(float* p, float a, float b, float c, float d) {
    asm volatile("red.global.add.v4.f32 [%0], {%1, %2, %3, %4};"
                 :: "l"(p), "f"(a), "f"(b), "f"(c), "f"(d) : "memory");
}

__global__ __launch_bounds__(256) void pin_util_kernel(
    const float* __restrict__ pos,
    const float* __restrict__ node_size_x,
    const float* __restrict__ node_size_y,
    const float* __restrict__ pin_weights,
    float* __restrict__ out)
{
    int i = blockIdx.x * 256 + threadIdx.x;
    if (i >= NUM_PHYSICAL) return;

    float nsx = node_size_x[i];
    float nsy = node_size_y[i];
    float x   = pos[i];
    float y   = pos[NUM_NODES + i];
    float pw  = pin_weights[i];

    float hx = 0.5f * fmaxf(nsx, SQRT2F);
    float hy = 0.5f * fmaxf(nsy, SQRT2F);
    float cx = x + 0.5f * nsx;
    float cy = y + 0.5f * nsy;
    float xmin = cx - hx, xmax = cx + hx;
    float ymin = cy - hy, ymax = cy + hy;

    // bin_size = 1.0, origin = 0.0 -> exact floor math
    int blx = max(0, (int)floorf(xmin));
    int bhx = min((int)floorf(xmax) + 1, NUM_BINS_X);
    int bly = max(0, (int)floorf(ymin));
    int bhy = min((int)floorf(ymax) + 1, NUM_BINS_Y);

    int nx = bhx - blx; nx = nx > KMAX ? KMAX : nx;
    int ny = bhy - bly; ny = ny > KMAX ? KMAX : ny;
    if (nx <= 0 || ny <= 0) return;

    // density * final scale folded together
    float dens = (OUT_SCALE * pw) / (4.0f * hx * hy);

    // Slot y-overlaps into 16B-segment-aligned positions.
    // Segment base = (bly & ~3); span occupies slots [off, off+ny) with off = bly&3.
    // off+ny-1 <= 3+3 = 6 < 8 -> at most two 16B segments.
    int off = bly & 3;
    int segbase = bly & ~3;
    float oslot[8];
    #pragma unroll
    for (int s = 0; s < 8; ++s) oslot[s] = 0.0f;
    #pragma unroll
    for (int k = 0; k < KMAX; ++k) {
        float b = (float)(bly + k);
        float ov = fminf(b + 1.0f, ymax) - fmaxf(b, ymin);
        if (k < ny) oslot[off + k] = ov;
    }
    bool two_segs = (off + ny) > 4;

    for (int kx = 0; kx < nx; ++kx) {
        float bx = (float)(blx + kx);
        float ovx = fminf(bx + 1.0f, xmax) - fmaxf(bx, xmin);
        float c = dens * ovx;
        float* seg = out + (blx + kx) * NUM_BINS_Y + segbase;

        red_v4f32(seg, c * oslot[0], c * oslot[1], c * oslot[2], c * oslot[3]);
        if (two_segs)
            red_v4f32(seg + 4, c * oslot[4], c * oslot[5], c * oslot[6], c * oslot[7]);
    }
}

extern "C" void kernel_launch(void* const* d_in, const int* in_sizes, int n_in,
                              void* d_out, int out_size) {
    const float* pos  = (const float*)d_in[0];
    const float* nsx  = (const float*)d_in[1];
    const float* nsy  = (const float*)d_in[2];
    const float* pw   = (const float*)d_in[3];
    float* out = (float*)d_out;

    // out_size = 1024*1024; zero it (poisoned by harness)
    int n4 = (NUM_BINS_X * NUM_BINS_Y) / 4;           // 262144
    zero_out_kernel<<<n4 / 256, 256>>>((float4*)out);

    int grid = (NUM_PHYSICAL + 255) / 256;
    pin_util_kernel<<<grid, 256>>>(pos, nsx, nsy, pw, out);
}